// round 7
// baseline (speedup 1.0000x reference)
#include <cuda_runtime.h>

// out[b,o] = ( x @ softmax(W,axis=1)^T > 0.5 )
// BIT-REPLICATION constraints (verified: 1 flip @ rel_err 4.888245e-4):
//  - softmax: XLA row-reduction tree replica (kernel 1, DO NOT REORDER)
//  - GEMM: per-output serial ascending-k fp32 fma.rn chain. FFMA2 lanes are
//    independent IEEE fma.rn, so packing outputs into lanes preserves chains.
// R7: DIAGONAL lane pairing -> both FFMA2 operands come directly from the
// LDS.128 data as 64-bit halves; only 4 b-pair swaps of prep per k-step.

#define M_DIM 4096
#define N_DIM 2048
#define K_DIM 2048

__device__ float g_w[(size_t)N_DIM * K_DIM];

// ---------------------------------------------------------------------------
// Kernel 1: XLA softmax replica (unchanged — bit-exact anchor).
// ---------------------------------------------------------------------------
__global__ __launch_bounds__(1024) void softmax_rows_kernel(const float* __restrict__ raw) {
    const int row = blockIdx.x;
    const int tid = threadIdx.x;
    const int lane = tid & 31;
    const int wid = tid >> 5;

    const float2* __restrict__ r2 =
        reinterpret_cast<const float2*>(raw + (size_t)row * K_DIM);
    float2* __restrict__ w2 = reinterpret_cast<float2*>(g_w + (size_t)row * K_DIM);

    const float2 v = r2[tid];

    __shared__ float s_part[32];
    __shared__ float s_bcast;

    float m = fmaxf(v.x, v.y);
#pragma unroll
    for (int off = 16; off > 0; off >>= 1)
        m = fmaxf(m, __shfl_down_sync(0xffffffffu, m, off));
    if (lane == 0) s_part[wid] = m;
    __syncthreads();
    if (wid == 0) {
        float t = s_part[lane];
#pragma unroll
        for (int off = 16; off > 0; off >>= 1)
            t = fmaxf(t, __shfl_down_sync(0xffffffffu, t, off));
        if (lane == 0) s_bcast = t;
    }
    __syncthreads();
    m = s_bcast;
    __syncthreads();

    const float e0 = expf(v.x - m);
    const float e1 = expf(v.y - m);

    float p = e0 + e1;
#pragma unroll
    for (int off = 16; off > 0; off >>= 1)
        p += __shfl_down_sync(0xffffffffu, p, off);
    if (lane == 0) s_part[wid] = p;
    __syncthreads();
    if (wid == 0) {
        float t = s_part[lane];
#pragma unroll
        for (int off = 16; off > 0; off >>= 1)
            t += __shfl_down_sync(0xffffffffu, t, off);
        if (lane == 0) s_bcast = t;
    }
    __syncthreads();
    const float S = s_bcast;

    float2 w;
    w.x = e0 / S;
    w.y = e1 / S;
    w2[tid] = w;
}

// ---------------------------------------------------------------------------
// Kernel 2: FFMA2 GEMM + threshold, diagonal lane pairing.
// 128x128 tile, BK=16, 256 threads, 8x8 microtile = 4 M-pairs x 4 N-pairs,
// 2 FFMA2 per 2x2 block (diag + anti-diag). Smem layouts identical to R4/R6.
// ---------------------------------------------------------------------------
#define BM 128
#define BN 128
#define BK 16
#define LDA (BM + 4)
#define NKT (K_DIM / BK)

typedef unsigned long long u64t;

__device__ __forceinline__ u64t swap_f32x2(u64t v) {
    u64t r;
    asm("{\n\t.reg .b32 lo, hi;\n\t"
        "mov.b64 {lo, hi}, %1;\n\t"
        "mov.b64 %0, {hi, lo};\n\t}"
        : "=l"(r) : "l"(v));
    return r;
}

#define FMA2(acc, a, b) \
    asm("fma.rn.f32x2 %0, %1, %2, %0;" : "+l"(acc) : "l"(a), "l"(b))

__global__ __launch_bounds__(256, 2) void gemm_thresh_kernel(const float* __restrict__ A,
                                                             float* __restrict__ C) {
    const float* __restrict__ B = g_w;

    __shared__ float As[2][BK][LDA];
    __shared__ float Bs[2][BK][LDA];

    const int tid = threadIdx.x;
    const int bm = blockIdx.y * BM;
    const int bn = blockIdx.x * BN;

    const int lrow0 = tid >> 2;
    const int lrow1 = lrow0 + 64;
    const int lcol = (tid & 3) * 4;

    const int ty = tid >> 4;  // 0..15 (M)
    const int tx = tid & 15;  // 0..15 (N)

    // acc_d[mp][np].lo = C(m0,n0), .hi = C(m1,n1)
    // acc_a[mp][np].lo = C(m0,n1), .hi = C(m1,n0)
    u64t acc_d[4][4], acc_a[4][4];
#pragma unroll
    for (int i = 0; i < 4; ++i)
#pragma unroll
        for (int j = 0; j < 4; ++j) { acc_d[i][j] = 0ull; acc_a[i][j] = 0ull; }

    const float* __restrict__ Ap0 = A + (size_t)(bm + lrow0) * K_DIM + lcol;
    const float* __restrict__ Ap1 = A + (size_t)(bm + lrow1) * K_DIM + lcol;
    const float* __restrict__ Bp0 = B + (size_t)(bn + lrow0) * K_DIM + lcol;
    const float* __restrict__ Bp1 = B + (size_t)(bn + lrow1) * K_DIM + lcol;

    float4 pa0 = *(const float4*)(Ap0);
    float4 pa1 = *(const float4*)(Ap1);
    float4 pb0 = *(const float4*)(Bp0);
    float4 pb1 = *(const float4*)(Bp1);

    int buf = 0;
    As[0][lcol + 0][lrow0] = pa0.x; As[0][lcol + 1][lrow0] = pa0.y;
    As[0][lcol + 2][lrow0] = pa0.z; As[0][lcol + 3][lrow0] = pa0.w;
    As[0][lcol + 0][lrow1] = pa1.x; As[0][lcol + 1][lrow1] = pa1.y;
    As[0][lcol + 2][lrow1] = pa1.z; As[0][lcol + 3][lrow1] = pa1.w;
    Bs[0][lcol + 0][lrow0] = pb0.x; Bs[0][lcol + 1][lrow0] = pb0.y;
    Bs[0][lcol + 2][lrow0] = pb0.z; Bs[0][lcol + 3][lrow0] = pb0.w;
    Bs[0][lcol + 0][lrow1] = pb1.x; Bs[0][lcol + 1][lrow1] = pb1.y;
    Bs[0][lcol + 2][lrow1] = pb1.z; Bs[0][lcol + 3][lrow1] = pb1.w;
    __syncthreads();

    for (int kt = 0; kt < NKT; ++kt) {
        const int ko = (kt + 1) * BK;
        const bool has_next = (kt + 1 < NKT);
        if (has_next) {
            pa0 = *(const float4*)(Ap0 + ko);
            pa1 = *(const float4*)(Ap1 + ko);
            pb0 = *(const float4*)(Bp0 + ko);
            pb1 = *(const float4*)(Bp1 + ko);
        }

#pragma unroll
        for (int k = 0; k < BK; ++k) {  // k strictly ascending: serial chains
            const ulonglong2 aq0 = *(const ulonglong2*)&As[buf][k][ty * 4];
            const ulonglong2 aq1 = *(const ulonglong2*)&As[buf][k][64 + ty * 4];
            const ulonglong2 bq0 = *(const ulonglong2*)&Bs[buf][k][tx * 4];
            const ulonglong2 bq1 = *(const ulonglong2*)&Bs[buf][k][64 + tx * 4];
            const u64t av[4] = {aq0.x, aq0.y, aq1.x, aq1.y};
            const u64t bv[4] = {bq0.x, bq0.y, bq1.x, bq1.y};
            u64t bw[4];
#pragma unroll
            for (int j = 0; j < 4; ++j) bw[j] = swap_f32x2(bv[j]);
#pragma unroll
            for (int i = 0; i < 4; ++i) {
#pragma unroll
                for (int j = 0; j < 4; ++j) {
                    FMA2(acc_d[i][j], av[i], bv[j]);
                    FMA2(acc_a[i][j], av[i], bw[j]);
                }
            }
        }

        if (has_next) {
            buf ^= 1;
            As[buf][lcol + 0][lrow0] = pa0.x; As[buf][lcol + 1][lrow0] = pa0.y;
            As[buf][lcol + 2][lrow0] = pa0.z; As[buf][lcol + 3][lrow0] = pa0.w;
            As[buf][lcol + 0][lrow1] = pa1.x; As[buf][lcol + 1][lrow1] = pa1.y;
            As[buf][lcol + 2][lrow1] = pa1.z; As[buf][lcol + 3][lrow1] = pa1.w;
            Bs[buf][lcol + 0][lrow0] = pb0.x; Bs[buf][lcol + 1][lrow0] = pb0.y;
            Bs[buf][lcol + 2][lrow0] = pb0.z; Bs[buf][lcol + 3][lrow0] = pb0.w;
            Bs[buf][lcol + 0][lrow1] = pb1.x; Bs[buf][lcol + 1][lrow1] = pb1.y;
            Bs[buf][lcol + 2][lrow1] = pb1.z; Bs[buf][lcol + 3][lrow1] = pb1.w;
            __syncthreads();
        }
    }

    // Epilogue: unpack diag/anti-diag lanes, threshold, float4 stores.
#pragma unroll
    for (int mp = 0; mp < 4; ++mp) {
        const int r0 = bm + ((mp < 2) ? ty * 4 : 64 + ty * 4) + (mp & 1) * 2;
        const int r1 = r0 + 1;

        float dlo[4], dhi[4], alo[4], ahi[4];
#pragma unroll
        for (int j = 0; j < 4; ++j) {
            asm("mov.b64 {%0, %1}, %2;" : "=f"(dlo[j]), "=f"(dhi[j]) : "l"(acc_d[mp][j]));
            asm("mov.b64 {%0, %1}, %2;" : "=f"(alo[j]), "=f"(ahi[j]) : "l"(acc_a[mp][j]));
        }

        float4 o;
        // row r0, cols tx*4..+3 : d.lo, a.lo per N-pair
        o.x = dlo[0] > 0.5f ? 1.f : 0.f;
        o.y = alo[0] > 0.5f ? 1.f : 0.f;
        o.z = dlo[1] > 0.5f ? 1.f : 0.f;
        o.w = alo[1] > 0.5f ? 1.f : 0.f;
        *(float4*)&C[(size_t)r0 * N_DIM + bn + tx * 4] = o;
        // row r0, cols 64+tx*4..+3
        o.x = dlo[2] > 0.5f ? 1.f : 0.f;
        o.y = alo[2] > 0.5f ? 1.f : 0.f;
        o.z = dlo[3] > 0.5f ? 1.f : 0.f;
        o.w = alo[3] > 0.5f ? 1.f : 0.f;
        *(float4*)&C[(size_t)r0 * N_DIM + bn + 64 + tx * 4] = o;
        // row r1, cols tx*4..+3 : a.hi, d.hi per N-pair
        o.x = ahi[0] > 0.5f ? 1.f : 0.f;
        o.y = dhi[0] > 0.5f ? 1.f : 0.f;
        o.z = ahi[1] > 0.5f ? 1.f : 0.f;
        o.w = dhi[1] > 0.5f ? 1.f : 0.f;
        *(float4*)&C[(size_t)r1 * N_DIM + bn + tx * 4] = o;
        // row r1, cols 64+tx*4..+3
        o.x = ahi[2] > 0.5f ? 1.f : 0.f;
        o.y = dhi[2] > 0.5f ? 1.f : 0.f;
        o.z = ahi[3] > 0.5f ? 1.f : 0.f;
        o.w = dhi[3] > 0.5f ? 1.f : 0.f;
        *(float4*)&C[(size_t)r1 * N_DIM + bn + 64 + tx * 4] = o;
    }
}

// ---------------------------------------------------------------------------
extern "C" void kernel_launch(void* const* d_in, const int* in_sizes, int n_in,
                              void* d_out, int out_size) {
    const float* x = (const float*)d_in[0];      // [4096, 2048]
    const float* raw_w = (const float*)d_in[1];  // [2048, 2048]
    float* out = (float*)d_out;                  // [4096, 2048]

    softmax_rows_kernel<<<N_DIM, 1024>>>(raw_w);

    dim3 grid(N_DIM / BN, M_DIM / BM);  // (16, 32)
    gemm_thresh_kernel<<<grid, 256>>>(x, out);
}